// round 16
// baseline (speedup 1.0000x reference)
#include <cuda_runtime.h>
#include <cuda_fp16.h>
#include <math.h>

// Problem constants
#define BB 2
#define SS 2048
#define EE 2048
#define HH 16
#define NOPE 128
#define ROPE_D 64
#define QHD 192          // NOPE + ROPE
#define LORA 512
#define VD 128
#define RWS (BB*SS)      // 4096 rows
#define QAW 3712         // fused q(3072) + kva(576->640 pad) width

// Scratch (device globals; no allocation allowed)
__device__ __half g_qkvah[(size_t)RWS * QAW];          // fused x@[wq|wkv_a], half (q roped in-place)
__device__ __half g_kpeh[(size_t)RWS * ROPE_D];        // roped k_pe, half
__device__ __half g_ckvh[(size_t)RWS * LORA];
__device__ __half g_kvh[(size_t)RWS * (HH * (NOPE + VD))];
__device__ __half g_aoh[(size_t)RWS * (HH * VD)];
__device__ __half g_xh[(size_t)RWS * EE];
__device__ __half g_wqaT[(size_t)QAW * 2048];          // [wq^T ; wkv_a^T(pad)]
__device__ __half g_wkvbT[(size_t)4096 * 512];
__device__ __half g_woT[(size_t)2048 * 2048];
__device__ float  g_cs[SS * ROPE_D];                   // cos[0..31], sin[32..63]

// ---------------- helpers ----------------
__device__ __forceinline__ void mma16(float* c, const unsigned* a, const unsigned* b) {
    asm volatile("mma.sync.aligned.m16n8k16.row.col.f32.f16.f16.f32 "
        "{%0,%1,%2,%3}, {%4,%5,%6,%7}, {%8,%9}, {%0,%1,%2,%3};"
        : "+f"(c[0]), "+f"(c[1]), "+f"(c[2]), "+f"(c[3])
        : "r"(a[0]), "r"(a[1]), "r"(a[2]), "r"(a[3]), "r"(b[0]), "r"(b[1]));
}
__device__ __forceinline__ void ldm_x4(unsigned* r, const void* p) {
    unsigned s = (unsigned)__cvta_generic_to_shared(p);
    asm volatile("ldmatrix.sync.aligned.m8n8.x4.shared.b16 {%0,%1,%2,%3}, [%4];"
        : "=r"(r[0]), "=r"(r[1]), "=r"(r[2]), "=r"(r[3]) : "r"(s));
}
__device__ __forceinline__ void ldm_x4t(unsigned* r, const void* p) {
    unsigned s = (unsigned)__cvta_generic_to_shared(p);
    asm volatile("ldmatrix.sync.aligned.m8n8.x4.trans.shared.b16 {%0,%1,%2,%3}, [%4];"
        : "=r"(r[0]), "=r"(r[1]), "=r"(r[2]), "=r"(r[3]) : "r"(s));
}
__device__ __forceinline__ void cp16(void* dst, const void* src) {
    unsigned d = (unsigned)__cvta_generic_to_shared(dst);
    asm volatile("cp.async.cg.shared.global [%0], [%1], 16;" :: "r"(d), "l"(src));
}
__device__ __forceinline__ void cp_commit() {
    asm volatile("cp.async.commit_group;");
}
template<int N> __device__ __forceinline__ void cp_wait() {
    asm volatile("cp.async.wait_group %0;" :: "n"(N));
}
__device__ __forceinline__ void st2o(float* p, float x, float y) {
    *(float2*)p = make_float2(x, y);
}
__device__ __forceinline__ void st2o(__half* p, float x, float y) {
    *(__half2*)p = __floats2half2_rn(x, y);
}
__device__ __forceinline__ unsigned packh2(float a, float b) {
    __half2 h = __floats2half2_rn(a, b);
    return *(unsigned*)&h;
}

// ---------------------------------------------------------------------------
// FP16 tensor-core GEMM (R11 shape): C[M,N] = A[M,K] @ BT[N,K]^T.
// 128x128 tile, BK=64, 256 thr = 8 warps (2Mx4N, 64x32 each), 3-stage cp.async.
// ---------------------------------------------------------------------------
#define ASTRH 72
#define STG_H (2 * 128 * ASTRH)       // halves per stage (A + B)
#define GSMEM (3 * STG_H * 2)         // 110592 bytes

template<typename OutT>
__global__ void __launch_bounds__(256, 2) hgemm(const __half* __restrict__ A,
                                                const __half* __restrict__ BT,
                                                OutT* __restrict__ C,
                                                int N, int K) {
    extern __shared__ __half hs[];

    int tid = threadIdx.x, wid = tid >> 5, lane = tid & 31;
    int bm = blockIdx.y * 128, bn = blockIdx.x * 128;
    int wm = (wid >> 2) * 64, wn = (wid & 3) * 32;
    int gr = lane >> 2, tg = lane & 3;

    int a_r = (lane & 7) + ((lane >> 3) & 1) * 8;   // ldmatrix x4 A row map
    int a_c = ((lane >> 4) & 1) * 8;
    int b_r = (lane & 7) + ((lane >> 4) & 1) * 8;   // ldmatrix x4 B (j-pair) map
    int b_c = ((lane >> 3) & 1) * 8;

    int nkb = K >> 6;

    auto issue = [&](int kb, int slot) {
        __half* sA = hs + slot * STG_H;
        __half* sB = sA + 128 * ASTRH;
        int k0 = kb * 64;
        #pragma unroll
        for (int p = 0; p < 4; p++) {
            int idx = tid + p * 256;          // 0..1023
            int row = idx >> 3, c = idx & 7;
            cp16(sA + row * ASTRH + c * 8, A + (size_t)(bm + row) * K + k0 + c * 8);
        }
        #pragma unroll
        for (int p = 0; p < 4; p++) {
            int idx = tid + p * 256;
            int row = idx >> 3, c = idx & 7;
            cp16(sB + row * ASTRH + c * 8, BT + (size_t)(bn + row) * K + k0 + c * 8);
        }
        cp_commit();
    };

    issue(0, 0);
    if (nkb > 1) issue(1, 1);

    float acc[4][4][4];
    #pragma unroll
    for (int i = 0; i < 4; i++)
        #pragma unroll
        for (int j = 0; j < 4; j++)
            #pragma unroll
            for (int t = 0; t < 4; t++) acc[i][j][t] = 0.f;

    int slot = 0;
    for (int kb = 0; kb < nkb; kb++) {
        if (kb + 1 < nkb) cp_wait<1>(); else cp_wait<0>();
        __syncthreads();
        if (kb + 2 < nkb) {
            int ns = slot + 2; if (ns >= 3) ns -= 3;
            issue(kb + 2, ns);
        }

        __half* sA = hs + slot * STG_H;
        __half* sB = sA + 128 * ASTRH;

        #pragma unroll
        for (int ks = 0; ks < 4; ks++) {
            int kk = ks * 16;
            unsigned a[4][4], b[2][4];
            #pragma unroll
            for (int i = 0; i < 4; i++)
                ldm_x4(a[i], sA + (wm + i * 16 + a_r) * ASTRH + kk + a_c);
            #pragma unroll
            for (int j = 0; j < 2; j++)
                ldm_x4(b[j], sB + (wn + j * 16 + b_r) * ASTRH + kk + b_c);
            #pragma unroll
            for (int i = 0; i < 4; i++)
                #pragma unroll
                for (int j = 0; j < 2; j++) {
                    mma16(acc[i][j * 2],     a[i], b[j]);
                    mma16(acc[i][j * 2 + 1], a[i], b[j] + 2);
                }
        }
        slot++; if (slot >= 3) slot = 0;
    }

    #pragma unroll
    for (int i = 0; i < 4; i++) {
        int r0 = bm + wm + i * 16 + gr;
        #pragma unroll
        for (int j = 0; j < 4; j++) {
            int cc = bn + wn + j * 8 + 2 * tg;
            if (cc < N) {
                st2o(C + (size_t)r0 * N + cc, acc[i][j][0], acc[i][j][1]);
                st2o(C + (size_t)(r0 + 8) * N + cc, acc[i][j][2], acc[i][j][3]);
            }
        }
    }
}

// ---------------------------------------------------------------------------
// Prep kernels (R11 versions)
// ---------------------------------------------------------------------------
__global__ void f2h_copy(const float* __restrict__ src, __half* __restrict__ dst,
                         int n4) {
    for (int i = blockIdx.x * blockDim.x + threadIdx.x; i < n4; i += gridDim.x * blockDim.x) {
        float4 v = *(const float4*)(src + i * 4);
        __half2* d = (__half2*)(dst + i * 4);
        d[0] = __floats2half2_rn(v.x, v.y);
        d[1] = __floats2half2_rn(v.z, v.w);
    }
}

__global__ void transpose_h(const float* __restrict__ src, __half* __restrict__ dst,
                            int K, int N, int Npad) {
    __shared__ float t[32][33];
    int kb = blockIdx.x * 32, nb = blockIdx.y * 32;
    int tx = threadIdx.x, ty = threadIdx.y;
    #pragma unroll
    for (int j = 0; j < 4; j++) {
        int k = kb + ty + j * 8, n = nb + tx;
        float v = 0.f;
        if (k < K && n < N) v = src[(size_t)k * N + n];
        t[ty + j * 8][tx] = v;
    }
    __syncthreads();
    #pragma unroll
    for (int j = 0; j < 4; j++) {
        int n = nb + ty + j * 8, k = kb + tx;
        if (n < Npad && k < K) dst[(size_t)n * K + k] = __float2half(t[tx][ty + j * 8]);
    }
}

__global__ void cs_table(float* __restrict__ cs) {
    int s = blockIdx.x, i = threadIdx.x;   // 32 threads
    float inv = powf(10000.f, -(float)i / 32.f);
    float sn, c;
    sincosf((float)s * inv, &sn, &c);
    cs[s * ROPE_D + i] = c;
    cs[s * ROPE_D + 32 + i] = sn;
}

// Fused: RMSNorm(kva) -> ckvh; rope q_pe IN-PLACE in qkva; rope k_pe -> kpeh
__global__ void __launch_bounds__(128) norm_rope(__half* __restrict__ qkva,
                                                 const float* __restrict__ kvs,
                                                 const float* __restrict__ cs,
                                                 __half* __restrict__ ckv,
                                                 __half* __restrict__ kpeh) {
    int r = blockIdx.x;
    int s = r % SS;
    int tid = threadIdx.x;
    __half* rowbase = qkva + (size_t)r * QAW;
    const __half* row = rowbase + 3072;
    const float* csr = cs + s * ROPE_D;

    float x[4];
    float ss = 0.f;
    #pragma unroll
    for (int j = 0; j < 4; j++) {
        x[j] = __half2float(row[tid + 128 * j]);
        ss += x[j] * x[j];
    }
    #pragma unroll
    for (int o = 16; o > 0; o >>= 1)
        ss += __shfl_xor_sync(0xffffffffu, ss, o);

    __shared__ float wsum[4];
    if ((tid & 31) == 0) wsum[tid >> 5] = ss;
    __syncthreads();
    float tot = wsum[0] + wsum[1] + wsum[2] + wsum[3];
    float rms = rsqrtf(tot / (float)LORA + 1e-6f);

    __half* orow = ckv + (size_t)r * LORA;
    #pragma unroll
    for (int j = 0; j < 4; j++) {
        int c = tid + 128 * j;
        orow[c] = __float2half(x[j] * rms * kvs[c]);
    }

    #pragma unroll
    for (int p = 0; p < 4; p++) {
        int i = tid + p * 128;
        int head = i >> 5, ii = i & 31;
        float c = csr[ii], sn = csr[ii + 32];
        int off = head * QHD + NOPE + ii;
        float x1 = __half2float(rowbase[off]), x2 = __half2float(rowbase[off + 32]);
        rowbase[off]      = __float2half(x1 * c - x2 * sn);
        rowbase[off + 32] = __float2half(x2 * c + x1 * sn);
    }
    if (tid < 32) {
        float c = csr[tid], sn = csr[tid + 32];
        const __half* kp = rowbase + 3072 + LORA;
        __half* ko = kpeh + (size_t)r * ROPE_D;
        float x1 = __half2float(kp[tid]), x2 = __half2float(kp[tid + 32]);
        ko[tid]      = __float2half(x1 * c - x2 * sn);
        ko[tid + 32] = __float2half(x2 * c + x1 * sn);
    }
}

// ---------------------------------------------------------------------------
// Flash attention (causal), FP16 mma. BM=128, BN=128, 256 thr = 8 warps.
// Q from qkva (roped in-place); P packed C->A in regs (FA2); exp2 softmax.
// K and V in SEPARATE cp.async groups: V load overlaps score compute.
// ---------------------------------------------------------------------------
#define FBM 128
#define FBN 128
#define KSTRH 200
#define VSTRH 136
#define SK_W (FBN * KSTRH)
#define SV_W (FBN * VSTRH)
#define FSMEM ((2*SK_W + 2*SV_W) * 2)

__global__ void __launch_bounds__(256, 1) flash_h(const __half* __restrict__ qkva,
                                                  const __half* __restrict__ kvh,
                                                  const __half* __restrict__ kpeh,
                                                  __half* __restrict__ aoh) {
    extern __shared__ __half fh[];
    __half* sK = fh;                    // [2][SK_W]
    __half* sV = fh + 2 * SK_W;         // [2][SV_W]

    int qt = gridDim.x - 1 - blockIdx.x;   // heavy tiles first
    int h = blockIdx.y, b = blockIdx.z;
    int tid = threadIdx.x, wid = tid >> 5, lane = tid & 31;
    int gr = lane >> 2, tg = lane & 3;
    int qbase = qt * FBM;
    int wrow = wid * 16;

    int a_r = (lane & 7) + ((lane >> 3) & 1) * 8;
    int a_c = ((lane >> 4) & 1) * 8;
    int k_r = (lane & 7) + ((lane >> 4) & 1) * 8;  // K x4 j-pair map
    int k_c = ((lane >> 3) & 1) * 8;
    int v_r = lane & 15;                            // V x4t map
    int v_c = ((lane >> 4) & 1) * 8;

    // --- stage Q through sK[0] overlay (128 x 200 halves = SK_W)
    __half* sQ = fh;
    #pragma unroll
    for (int p = 0; p < 12; p++) {
        int idx = tid + p * 256;           // 0..3071
        int row = idx / 24, c = idx - row * 24;
        int r = b * SS + qbase + row;
        cp16(sQ + row * KSTRH + c * 8,
             qkva + (size_t)r * QAW + h * QHD + c * 8);
    }
    cp_commit();
    cp_wait<0>();
    __syncthreads();

    unsigned qf[12][4];
    #pragma unroll
    for (int ks = 0; ks < 12; ks++)
        ldm_x4(qf[ks], sQ + (wrow + a_r) * KSTRH + ks * 16 + a_c);
    __syncthreads();   // Q consumed; sK area free

    // K and V committed as SEPARATE groups (K first, then V)
    auto load_kv = [&](int kbase, int stg) {
        __half* K = sK + stg * SK_W;
        __half* V = sV + stg * SV_W;
        #pragma unroll
        for (int p = 0; p < 12; p++) {
            int idx = tid + p * 256;       // 0..3071
            int row = idx / 24, c = idx - row * 24;
            int r = b * SS + kbase + row;
            const __half* src = (c < 16)
                ? kvh  + (size_t)r * (HH * (NOPE + VD)) + h * (NOPE + VD) + c * 8
                : kpeh + (size_t)r * ROPE_D + (c - 16) * 8;
            cp16(K + row * KSTRH + c * 8, src);
        }
        cp_commit();                       // group: K(kbase)
        #pragma unroll
        for (int p = 0; p < 8; p++) {
            int idx = tid + p * 256;       // 0..2047
            int row = idx >> 4, c = idx & 15;
            int r = b * SS + kbase + row;
            cp16(V + row * VSTRH + c * 8,
                 kvh + (size_t)r * (HH * (NOPE + VD)) + h * (NOPE + VD) + NOPE + c * 8);
        }
        cp_commit();                       // group: V(kbase)
    };

    float o[16][4];
    #pragma unroll
    for (int n = 0; n < 16; n++)
        #pragma unroll
        for (int t = 0; t < 4; t++) o[n][t] = 0.f;
    float m0 = -1e30f, m1 = -1e30f, l0 = 0.f, l1 = 0.f;
    // scale * log2(e): softmax in exp2 domain
    const float scale = 0.07216878364870323f * 1.4426950408889634f;

    int ktmax = qt + 1;
    load_kv(0, 0);

    for (int kt = 0; kt < ktmax; kt++) {
        int kbase = kt * FBN;
        int stg = kt & 1;
        bool more = (kt + 1 < ktmax);

        // K(kt) ready (V(kt) may still be in flight)
        cp_wait<1>();
        __syncthreads();
        if (more) load_kv(kbase + FBN, stg ^ 1);

        __half* K = sK + stg * SK_W;
        __half* V = sV + stg * SV_W;

        // ---- scores: S = Q K^T (16 rows x 128 cols per warp) ----
        float sacc[16][4];
        #pragma unroll
        for (int j = 0; j < 16; j++)
            #pragma unroll
            for (int t = 0; t < 4; t++) sacc[j][t] = 0.f;

        #pragma unroll
        for (int ks = 0; ks < 12; ks++) {
            int kk = ks * 16;
            #pragma unroll
            for (int j = 0; j < 16; j += 2) {
                unsigned bb[4];
                ldm_x4(bb, K + (j * 8 + k_r) * KSTRH + kk + k_c);
                mma16(sacc[j],     qf[ks], bb);
                mma16(sacc[j + 1], qf[ks], bb + 2);
            }
        }

        // ---- scale + (diag-only) causal mask + online softmax (exp2) ----
        int qr0 = qbase + wrow + gr;
        int qr1 = qr0 + 8;
        float mx0 = -1e30f, mx1 = -1e30f;
        if (kt < qt) {
            #pragma unroll
            for (int j = 0; j < 16; j++) {
                sacc[j][0] *= scale; sacc[j][1] *= scale;
                sacc[j][2] *= scale; sacc[j][3] *= scale;
                mx0 = fmaxf(mx0, fmaxf(sacc[j][0], sacc[j][1]));
                mx1 = fmaxf(mx1, fmaxf(sacc[j][2], sacc[j][3]));
            }
        } else {
            #pragma unroll
            for (int j = 0; j < 16; j++) {
                int c0 = kbase + j * 8 + 2 * tg;
                sacc[j][0] = (c0     <= qr0) ? sacc[j][0] * scale : -1e30f;
                sacc[j][1] = (c0 + 1 <= qr0) ? sacc[j][1] * scale : -1e30f;
                sacc[j][2] = (c0     <= qr1) ? sacc[j][2] * scale : -1e30f;
                sacc[j][3] = (c0 + 1 <= qr1) ? sacc[j][3] * scale : -1e30f;
                mx0 = fmaxf(mx0, fmaxf(sacc[j][0], sacc[j][1]));
                mx1 = fmaxf(mx1, fmaxf(sacc[j][2], sacc[j][3]));
            }
        }
        mx0 = fmaxf(mx0, __shfl_xor_sync(0xffffffffu, mx0, 1));
        mx0 = fmaxf(mx0, __shfl_xor_sync(0xffffffffu, mx0, 2));
        mx1 = fmaxf(mx1, __shfl_xor_sync(0xffffffffu, mx1, 1));
        mx1 = fmaxf(mx1, __shfl_xor_sync(0xffffffffu, mx1, 2));

        float mn0 = fmaxf(m0, mx0), mn1 = fmaxf(m1, mx1);
        float f0 = exp2f(m0 - mn0), f1 = exp2f(m1 - mn1);
        m0 = mn0; m1 = mn1;

        // exp2 + pack P into A-fragments (C->A register layout identity)
        unsigned pa[8][4];
        float s0 = 0.f, s1 = 0.f;
        #pragma unroll
        for (int j2 = 0; j2 < 8; j2++) {
            float p00 = exp2f(sacc[2*j2][0]   - mn0);
            float p01 = exp2f(sacc[2*j2][1]   - mn0);
            float p02 = exp2f(sacc[2*j2][2]   - mn1);
            float p03 = exp2f(sacc[2*j2][3]   - mn1);
            float p10 = exp2f(sacc[2*j2+1][0] - mn0);
            float p11 = exp2f(sacc[2*j2+1][1] - mn0);
            float p12 = exp2f(sacc[2*j2+1][2] - mn1);
            float p13 = exp2f(sacc[2*j2+1][3] - mn1);
            s0 += p00 + p01 + p10 + p11;
            s1 += p02 + p03 + p12 + p13;
            pa[j2][0] = packh2(p00, p01);
            pa[j2][1] = packh2(p02, p03);
            pa[j2][2] = packh2(p10, p11);
            pa[j2][3] = packh2(p12, p13);
        }
        s0 += __shfl_xor_sync(0xffffffffu, s0, 1);
        s0 += __shfl_xor_sync(0xffffffffu, s0, 2);
        s1 += __shfl_xor_sync(0xffffffffu, s1, 1);
        s1 += __shfl_xor_sync(0xffffffffu, s1, 2);
        l0 = l0 * f0 + s0;
        l1 = l1 * f1 + s1;

        #pragma unroll
        for (int n = 0; n < 16; n++) {
            o[n][0] *= f0; o[n][1] *= f0; o[n][2] *= f1; o[n][3] *= f1;
        }

        // V(kt) ready: outstanding = {V(kt), K(kt+1), V(kt+1)} if more, else {V(kt)}
        if (more) cp_wait<2>(); else cp_wait<0>();
        __syncthreads();

        // ---- PV: O += P V (16 rows x 128 cols per warp), P from registers ----
        #pragma unroll
        for (int ks = 0; ks < 8; ks++) {
            int kk = ks * 16;
            #pragma unroll
            for (int n = 0; n < 16; n += 2) {
                unsigned bb[4];
                ldm_x4t(bb, V + (kk + v_r) * VSTRH + n * 8 + v_c);
                mma16(o[n],     pa[ks], bb);
                mma16(o[n + 1], pa[ks], bb + 2);
            }
        }
    }

    // epilogue -> half
    float inv0 = 1.f / l0, inv1 = 1.f / l1;
    size_t r0 = (size_t)(b * SS + qbase + wrow + gr) * (HH * VD);
    size_t r1 = r0 + 8 * (HH * VD);
    #pragma unroll
    for (int n = 0; n < 16; n++) {
        int cc = h * VD + n * 8 + 2 * tg;
        *(__half2*)(aoh + r0 + cc) = __floats2half2_rn(o[n][0] * inv0, o[n][1] * inv0);
        *(__half2*)(aoh + r1 + cc) = __floats2half2_rn(o[n][2] * inv1, o[n][3] * inv1);
    }
}

// ---------------------------------------------------------------------------
extern "C" void kernel_launch(void* const* d_in, const int* in_sizes, int n_in,
                              void* d_out, int out_size) {
    const float* x     = (const float*)d_in[0];
    const float* wq    = (const float*)d_in[1];
    const float* wkv_a = (const float*)d_in[2];
    const float* wkv_b = (const float*)d_in[3];
    const float* wo    = (const float*)d_in[4];
    const float* kvs   = (const float*)d_in[5];
    float* out = (float*)d_out;

    float *cs;
    __half *qkvah, *kpeh, *ckvh, *kvh, *aoh, *xh, *wqaT, *wkvbT, *woT;
    cudaGetSymbolAddress((void**)&qkvah, g_qkvah);
    cudaGetSymbolAddress((void**)&cs,    g_cs);
    cudaGetSymbolAddress((void**)&kpeh,  g_kpeh);
    cudaGetSymbolAddress((void**)&ckvh,  g_ckvh);
    cudaGetSymbolAddress((void**)&kvh,   g_kvh);
    cudaGetSymbolAddress((void**)&aoh,   g_aoh);
    cudaGetSymbolAddress((void**)&xh,    g_xh);
    cudaGetSymbolAddress((void**)&wqaT,  g_wqaT);
    cudaGetSymbolAddress((void**)&wkvbT, g_wkvbT);
    cudaGetSymbolAddress((void**)&woT,   g_woT);

    static bool attr_done = false;
    if (!attr_done) {
        cudaFuncSetAttribute(flash_h,
                             cudaFuncAttributeMaxDynamicSharedMemorySize, (int)FSMEM);
        cudaFuncSetAttribute(hgemm<float>,
                             cudaFuncAttributeMaxDynamicSharedMemorySize, (int)GSMEM);
        cudaFuncSetAttribute(hgemm<__half>,
                             cudaFuncAttributeMaxDynamicSharedMemorySize, (int)GSMEM);
        attr_done = true;
    }

    // prep
    f2h_copy<<<1024, 256>>>(x, xh, RWS * EE / 4);
    cs_table<<<SS, 32>>>(cs);
    transpose_h<<<dim3(64, 96),  dim3(32, 8)>>>(wq,    wqaT,               2048, 3072, 3072);
    transpose_h<<<dim3(64, 20),  dim3(32, 8)>>>(wkv_a, wqaT + (size_t)3072 * 2048, 2048, 576, 640);
    transpose_h<<<dim3(16, 128), dim3(32, 8)>>>(wkv_b, wkvbT, 512,  4096, 4096);
    transpose_h<<<dim3(64, 64),  dim3(32, 8)>>>(wo,    woT,   2048, 2048, 2048);

    // qkva = x @ [wq | wkv_a] : [4096, 3712] half
    hgemm<__half><<<dim3(QAW / 128, 32), 256, GSMEM>>>(xh, wqaT, qkvah, QAW, 2048);
    // fused rmsnorm + in-place q rope + k_pe rope
    norm_rope<<<RWS, 128>>>(qkvah, kvs, cs, ckvh, kpeh);
    // kvh = ckv @ wkv_b : [4096, 4096] half
    hgemm<__half><<<dim3(32, 32), 256, GSMEM>>>(ckvh, wkvbT, kvh, 4096, 512);
    // attention -> aoh : [4096, 2048] half
    flash_h<<<dim3(SS / FBM, HH, BB), 256, FSMEM>>>(qkvah, kvh, kpeh, aoh);
    // out = ao @ wo : [4096, 2048] fp32
    hgemm<float><<<dim3(16, 32), 256, GSMEM>>>(aoh, woT, out, 2048, 2048);
}

// round 17
// speedup vs baseline: 1.0394x; 1.0394x over previous
#include <cuda_runtime.h>
#include <cuda_fp16.h>
#include <math.h>

// Problem constants
#define BB 2
#define SS 2048
#define EE 2048
#define HH 16
#define NOPE 128
#define ROPE_D 64
#define QHD 192          // NOPE + ROPE
#define LORA 512
#define VD 128
#define RWS (BB*SS)      // 4096 rows
#define QAW 3712         // fused q(3072) + kva(576->640 pad) width

// Scratch (device globals; no allocation allowed)
__device__ __half g_qkvah[(size_t)RWS * QAW];          // fused x@[wq|wkv_a], half (q roped in-place)
__device__ __half g_kpeh[(size_t)RWS * ROPE_D];        // roped k_pe, half
__device__ __half g_ckvh[(size_t)RWS * LORA];
__device__ __half g_kvh[(size_t)RWS * (HH * (NOPE + VD))];
__device__ __half g_aoh[(size_t)RWS * (HH * VD)];
__device__ __half g_xh[(size_t)RWS * EE];
__device__ __half g_wqaT[(size_t)QAW * 2048];          // [wq^T ; wkv_a^T(pad)]
__device__ __half g_wkvbT[(size_t)4096 * 512];
__device__ __half g_woT[(size_t)2048 * 2048];
__device__ float  g_cs[SS * ROPE_D];                   // cos[0..31], sin[32..63]

// ---------------- helpers ----------------
__device__ __forceinline__ void mma16(float* c, const unsigned* a, const unsigned* b) {
    asm volatile("mma.sync.aligned.m16n8k16.row.col.f32.f16.f16.f32 "
        "{%0,%1,%2,%3}, {%4,%5,%6,%7}, {%8,%9}, {%0,%1,%2,%3};"
        : "+f"(c[0]), "+f"(c[1]), "+f"(c[2]), "+f"(c[3])
        : "r"(a[0]), "r"(a[1]), "r"(a[2]), "r"(a[3]), "r"(b[0]), "r"(b[1]));
}
__device__ __forceinline__ void ldm_x4(unsigned* r, const void* p) {
    unsigned s = (unsigned)__cvta_generic_to_shared(p);
    asm volatile("ldmatrix.sync.aligned.m8n8.x4.shared.b16 {%0,%1,%2,%3}, [%4];"
        : "=r"(r[0]), "=r"(r[1]), "=r"(r[2]), "=r"(r[3]) : "r"(s));
}
__device__ __forceinline__ void ldm_x4t(unsigned* r, const void* p) {
    unsigned s = (unsigned)__cvta_generic_to_shared(p);
    asm volatile("ldmatrix.sync.aligned.m8n8.x4.trans.shared.b16 {%0,%1,%2,%3}, [%4];"
        : "=r"(r[0]), "=r"(r[1]), "=r"(r[2]), "=r"(r[3]) : "r"(s));
}
__device__ __forceinline__ void cp16(void* dst, const void* src) {
    unsigned d = (unsigned)__cvta_generic_to_shared(dst);
    asm volatile("cp.async.cg.shared.global [%0], [%1], 16;" :: "r"(d), "l"(src));
}
__device__ __forceinline__ void cp_commit() {
    asm volatile("cp.async.commit_group;");
}
template<int N> __device__ __forceinline__ void cp_wait() {
    asm volatile("cp.async.wait_group %0;" :: "n"(N));
}
__device__ __forceinline__ void st2o(float* p, float x, float y) {
    *(float2*)p = make_float2(x, y);
}
__device__ __forceinline__ void st2o(__half* p, float x, float y) {
    *(__half2*)p = __floats2half2_rn(x, y);
}
__device__ __forceinline__ unsigned packh2(float a, float b) {
    __half2 h = __floats2half2_rn(a, b);
    return *(unsigned*)&h;
}

// ---------------------------------------------------------------------------
// FP16 tensor-core GEMM (R11 shape, untouched): C[M,N] = A[M,K] @ BT[N,K]^T.
// 128x128 tile, BK=64, 256 thr = 8 warps (2Mx4N, 64x32 each), 3-stage cp.async.
// ---------------------------------------------------------------------------
#define ASTRH 72
#define STG_H (2 * 128 * ASTRH)       // halves per stage (A + B)
#define GSMEM (3 * STG_H * 2)         // 110592 bytes

template<typename OutT>
__global__ void __launch_bounds__(256, 2) hgemm(const __half* __restrict__ A,
                                                const __half* __restrict__ BT,
                                                OutT* __restrict__ C,
                                                int N, int K) {
    extern __shared__ __half hs[];

    int tid = threadIdx.x, wid = tid >> 5, lane = tid & 31;
    int bm = blockIdx.y * 128, bn = blockIdx.x * 128;
    int wm = (wid >> 2) * 64, wn = (wid & 3) * 32;
    int gr = lane >> 2, tg = lane & 3;

    int a_r = (lane & 7) + ((lane >> 3) & 1) * 8;   // ldmatrix x4 A row map
    int a_c = ((lane >> 4) & 1) * 8;
    int b_r = (lane & 7) + ((lane >> 4) & 1) * 8;   // ldmatrix x4 B (j-pair) map
    int b_c = ((lane >> 3) & 1) * 8;

    int nkb = K >> 6;

    auto issue = [&](int kb, int slot) {
        __half* sA = hs + slot * STG_H;
        __half* sB = sA + 128 * ASTRH;
        int k0 = kb * 64;
        #pragma unroll
        for (int p = 0; p < 4; p++) {
            int idx = tid + p * 256;          // 0..1023
            int row = idx >> 3, c = idx & 7;
            cp16(sA + row * ASTRH + c * 8, A + (size_t)(bm + row) * K + k0 + c * 8);
        }
        #pragma unroll
        for (int p = 0; p < 4; p++) {
            int idx = tid + p * 256;
            int row = idx >> 3, c = idx & 7;
            cp16(sB + row * ASTRH + c * 8, BT + (size_t)(bn + row) * K + k0 + c * 8);
        }
        cp_commit();
    };

    issue(0, 0);
    if (nkb > 1) issue(1, 1);

    float acc[4][4][4];
    #pragma unroll
    for (int i = 0; i < 4; i++)
        #pragma unroll
        for (int j = 0; j < 4; j++)
            #pragma unroll
            for (int t = 0; t < 4; t++) acc[i][j][t] = 0.f;

    int slot = 0;
    for (int kb = 0; kb < nkb; kb++) {
        if (kb + 1 < nkb) cp_wait<1>(); else cp_wait<0>();
        __syncthreads();
        if (kb + 2 < nkb) {
            int ns = slot + 2; if (ns >= 3) ns -= 3;
            issue(kb + 2, ns);
        }

        __half* sA = hs + slot * STG_H;
        __half* sB = sA + 128 * ASTRH;

        #pragma unroll
        for (int ks = 0; ks < 4; ks++) {
            int kk = ks * 16;
            unsigned a[4][4], b[2][4];
            #pragma unroll
            for (int i = 0; i < 4; i++)
                ldm_x4(a[i], sA + (wm + i * 16 + a_r) * ASTRH + kk + a_c);
            #pragma unroll
            for (int j = 0; j < 2; j++)
                ldm_x4(b[j], sB + (wn + j * 16 + b_r) * ASTRH + kk + b_c);
            #pragma unroll
            for (int i = 0; i < 4; i++)
                #pragma unroll
                for (int j = 0; j < 2; j++) {
                    mma16(acc[i][j * 2],     a[i], b[j]);
                    mma16(acc[i][j * 2 + 1], a[i], b[j] + 2);
                }
        }
        slot++; if (slot >= 3) slot = 0;
    }

    #pragma unroll
    for (int i = 0; i < 4; i++) {
        int r0 = bm + wm + i * 16 + gr;
        #pragma unroll
        for (int j = 0; j < 4; j++) {
            int cc = bn + wn + j * 8 + 2 * tg;
            if (cc < N) {
                st2o(C + (size_t)r0 * N + cc, acc[i][j][0], acc[i][j][1]);
                st2o(C + (size_t)(r0 + 8) * N + cc, acc[i][j][2], acc[i][j][3]);
            }
        }
    }
}

// ---------------------------------------------------------------------------
// Fused prep: f2h(x) + cos/sin table + 4 weight transposes, ONE launch.
// Region-dispatched on blockIdx.x. 256 threads.
// ---------------------------------------------------------------------------
__device__ __forceinline__ void tr_body(const float* __restrict__ src,
                                        __half* __restrict__ dst,
                                        int K, int N, int Npad,
                                        int kb, int nb, int tid,
                                        float (*t)[33]) {
    int tx = tid & 31, ty = tid >> 5;
    #pragma unroll
    for (int j = 0; j < 4; j++) {
        int k = kb + ty + j * 8, n = nb + tx;
        float v = 0.f;
        if (k < K && n < N) v = src[(size_t)k * N + n];
        t[ty + j * 8][tx] = v;
    }
    __syncthreads();
    #pragma unroll
    for (int j = 0; j < 4; j++) {
        int n = nb + ty + j * 8, k = kb + tx;
        if (n < Npad && k < K) dst[(size_t)n * K + k] = __float2half(t[tx][ty + j * 8]);
    }
}

#define PREP_F2H   1024
#define PREP_CS    256
#define PREP_WQ    6144   // 64 x 96
#define PREP_WA    1280   // 64 x 20
#define PREP_WB    2048   // 16 x 128
#define PREP_WO    4096   // 64 x 64
#define PREP_GRID  (PREP_F2H + PREP_CS + PREP_WQ + PREP_WA + PREP_WB + PREP_WO)

__global__ void __launch_bounds__(256) prep_all(const float* __restrict__ x,
                                                const float* __restrict__ wq,
                                                const float* __restrict__ wkv_a,
                                                const float* __restrict__ wkv_b,
                                                const float* __restrict__ wo,
                                                __half* __restrict__ xh,
                                                __half* __restrict__ wqaT,
                                                __half* __restrict__ wkvbT,
                                                __half* __restrict__ woT,
                                                float* __restrict__ cs) {
    __shared__ float t[32][33];
    int bid = blockIdx.x;
    int tid = threadIdx.x;

    if (bid < PREP_F2H) {
        int n4 = RWS * EE / 4;
        for (int i = bid * 256 + tid; i < n4; i += PREP_F2H * 256) {
            float4 v = *(const float4*)(x + (size_t)i * 4);
            __half2* d = (__half2*)(xh + (size_t)i * 4);
            d[0] = __floats2half2_rn(v.x, v.y);
            d[1] = __floats2half2_rn(v.z, v.w);
        }
        return;
    }
    bid -= PREP_F2H;
    if (bid < PREP_CS) {
        int s = bid * 8 + (tid >> 5);
        int i = tid & 31;
        float inv = powf(10000.f, -(float)i / 32.f);
        float sn, c;
        sincosf((float)s * inv, &sn, &c);
        cs[s * ROPE_D + i] = c;
        cs[s * ROPE_D + 32 + i] = sn;
        return;
    }
    bid -= PREP_CS;
    if (bid < PREP_WQ) {
        tr_body(wq, wqaT, 2048, 3072, 3072, (bid & 63) * 32, (bid >> 6) * 32, tid, t);
        return;
    }
    bid -= PREP_WQ;
    if (bid < PREP_WA) {
        tr_body(wkv_a, wqaT + (size_t)3072 * 2048, 2048, 576, 640,
                (bid & 63) * 32, (bid >> 6) * 32, tid, t);
        return;
    }
    bid -= PREP_WA;
    if (bid < PREP_WB) {
        tr_body(wkv_b, wkvbT, 512, 4096, 4096, (bid & 15) * 32, (bid >> 4) * 32, tid, t);
        return;
    }
    bid -= PREP_WB;
    tr_body(wo, woT, 2048, 2048, 2048, (bid & 63) * 32, (bid >> 6) * 32, tid, t);
}

// Fused: RMSNorm(kva) -> ckvh; rope q_pe IN-PLACE in qkva; rope k_pe -> kpeh
__global__ void __launch_bounds__(128) norm_rope(__half* __restrict__ qkva,
                                                 const float* __restrict__ kvs,
                                                 const float* __restrict__ cs,
                                                 __half* __restrict__ ckv,
                                                 __half* __restrict__ kpeh) {
    int r = blockIdx.x;
    int s = r % SS;
    int tid = threadIdx.x;
    __half* rowbase = qkva + (size_t)r * QAW;
    const __half* row = rowbase + 3072;
    const float* csr = cs + s * ROPE_D;

    float x[4];
    float ss = 0.f;
    #pragma unroll
    for (int j = 0; j < 4; j++) {
        x[j] = __half2float(row[tid + 128 * j]);
        ss += x[j] * x[j];
    }
    #pragma unroll
    for (int o = 16; o > 0; o >>= 1)
        ss += __shfl_xor_sync(0xffffffffu, ss, o);

    __shared__ float wsum[4];
    if ((tid & 31) == 0) wsum[tid >> 5] = ss;
    __syncthreads();
    float tot = wsum[0] + wsum[1] + wsum[2] + wsum[3];
    float rms = rsqrtf(tot / (float)LORA + 1e-6f);

    __half* orow = ckv + (size_t)r * LORA;
    #pragma unroll
    for (int j = 0; j < 4; j++) {
        int c = tid + 128 * j;
        orow[c] = __float2half(x[j] * rms * kvs[c]);
    }

    #pragma unroll
    for (int p = 0; p < 4; p++) {
        int i = tid + p * 128;
        int head = i >> 5, ii = i & 31;
        float c = csr[ii], sn = csr[ii + 32];
        int off = head * QHD + NOPE + ii;
        float x1 = __half2float(rowbase[off]), x2 = __half2float(rowbase[off + 32]);
        rowbase[off]      = __float2half(x1 * c - x2 * sn);
        rowbase[off + 32] = __float2half(x2 * c + x1 * sn);
    }
    if (tid < 32) {
        float c = csr[tid], sn = csr[tid + 32];
        const __half* kp = rowbase + 3072 + LORA;
        __half* ko = kpeh + (size_t)r * ROPE_D;
        float x1 = __half2float(kp[tid]), x2 = __half2float(kp[tid + 32]);
        ko[tid]      = __float2half(x1 * c - x2 * sn);
        ko[tid + 32] = __float2half(x2 * c + x1 * sn);
    }
}

// ---------------------------------------------------------------------------
// Flash attention (R11 exact): BM=128, BN=128, 256 thr = 8 warps.
// Q from qkva (roped in-place); P packed C->A in regs (FA2); exp2 softmax;
// K/V double-buffered via cp.async (single combined group per tile).
// ---------------------------------------------------------------------------
#define FBM 128
#define FBN 128
#define KSTRH 200
#define VSTRH 136
#define SK_W (FBN * KSTRH)
#define SV_W (FBN * VSTRH)
#define FSMEM ((2*SK_W + 2*SV_W) * 2)

__global__ void __launch_bounds__(256, 1) flash_h(const __half* __restrict__ qkva,
                                                  const __half* __restrict__ kvh,
                                                  const __half* __restrict__ kpeh,
                                                  __half* __restrict__ aoh) {
    extern __shared__ __half fh[];
    __half* sK = fh;                    // [2][SK_W]
    __half* sV = fh + 2 * SK_W;         // [2][SV_W]

    int qt = gridDim.x - 1 - blockIdx.x;   // heavy tiles first
    int h = blockIdx.y, b = blockIdx.z;
    int tid = threadIdx.x, wid = tid >> 5, lane = tid & 31;
    int gr = lane >> 2, tg = lane & 3;
    int qbase = qt * FBM;
    int wrow = wid * 16;

    int a_r = (lane & 7) + ((lane >> 3) & 1) * 8;
    int a_c = ((lane >> 4) & 1) * 8;
    int k_r = (lane & 7) + ((lane >> 4) & 1) * 8;  // K x4 j-pair map
    int k_c = ((lane >> 3) & 1) * 8;
    int v_r = lane & 15;                            // V x4t map
    int v_c = ((lane >> 4) & 1) * 8;

    // --- stage Q through sK[0] overlay (128 x 200 halves = SK_W)
    __half* sQ = fh;
    #pragma unroll
    for (int p = 0; p < 12; p++) {
        int idx = tid + p * 256;           // 0..3071
        int row = idx / 24, c = idx - row * 24;
        int r = b * SS + qbase + row;
        cp16(sQ + row * KSTRH + c * 8,
             qkva + (size_t)r * QAW + h * QHD + c * 8);
    }
    cp_commit();
    cp_wait<0>();
    __syncthreads();

    unsigned qf[12][4];
    #pragma unroll
    for (int ks = 0; ks < 12; ks++)
        ldm_x4(qf[ks], sQ + (wrow + a_r) * KSTRH + ks * 16 + a_c);
    __syncthreads();   // Q consumed; sK area free

    auto load_kv = [&](int kbase, int stg) {
        __half* K = sK + stg * SK_W;
        __half* V = sV + stg * SV_W;
        #pragma unroll
        for (int p = 0; p < 12; p++) {
            int idx = tid + p * 256;       // 0..3071
            int row = idx / 24, c = idx - row * 24;
            int r = b * SS + kbase + row;
            const __half* src = (c < 16)
                ? kvh  + (size_t)r * (HH * (NOPE + VD)) + h * (NOPE + VD) + c * 8
                : kpeh + (size_t)r * ROPE_D + (c - 16) * 8;
            cp16(K + row * KSTRH + c * 8, src);
        }
        #pragma unroll
        for (int p = 0; p < 8; p++) {
            int idx = tid + p * 256;       // 0..2047
            int row = idx >> 4, c = idx & 15;
            int r = b * SS + kbase + row;
            cp16(V + row * VSTRH + c * 8,
                 kvh + (size_t)r * (HH * (NOPE + VD)) + h * (NOPE + VD) + NOPE + c * 8);
        }
        cp_commit();
    };

    float o[16][4];
    #pragma unroll
    for (int n = 0; n < 16; n++)
        #pragma unroll
        for (int t = 0; t < 4; t++) o[n][t] = 0.f;
    float m0 = -1e30f, m1 = -1e30f, l0 = 0.f, l1 = 0.f;
    // scale * log2(e): softmax in exp2 domain
    const float scale = 0.07216878364870323f * 1.4426950408889634f;

    int ktmax = qt + 1;
    load_kv(0, 0);

    for (int kt = 0; kt < ktmax; kt++) {
        int kbase = kt * FBN;
        int stg = kt & 1;
        cp_wait<0>();
        __syncthreads();
        if (kt + 1 < ktmax) load_kv(kbase + FBN, stg ^ 1);

        __half* K = sK + stg * SK_W;
        __half* V = sV + stg * SV_W;

        // ---- scores: S = Q K^T (16 rows x 128 cols per warp) ----
        float sacc[16][4];
        #pragma unroll
        for (int j = 0; j < 16; j++)
            #pragma unroll
            for (int t = 0; t < 4; t++) sacc[j][t] = 0.f;

        #pragma unroll
        for (int ks = 0; ks < 12; ks++) {
            int kk = ks * 16;
            #pragma unroll
            for (int j = 0; j < 16; j += 2) {
                unsigned bb[4];
                ldm_x4(bb, K + (j * 8 + k_r) * KSTRH + kk + k_c);
                mma16(sacc[j],     qf[ks], bb);
                mma16(sacc[j + 1], qf[ks], bb + 2);
            }
        }

        // ---- scale + (diag-only) causal mask + online softmax (exp2) ----
        int qr0 = qbase + wrow + gr;
        int qr1 = qr0 + 8;
        float mx0 = -1e30f, mx1 = -1e30f;
        if (kt < qt) {
            #pragma unroll
            for (int j = 0; j < 16; j++) {
                sacc[j][0] *= scale; sacc[j][1] *= scale;
                sacc[j][2] *= scale; sacc[j][3] *= scale;
                mx0 = fmaxf(mx0, fmaxf(sacc[j][0], sacc[j][1]));
                mx1 = fmaxf(mx1, fmaxf(sacc[j][2], sacc[j][3]));
            }
        } else {
            #pragma unroll
            for (int j = 0; j < 16; j++) {
                int c0 = kbase + j * 8 + 2 * tg;
                sacc[j][0] = (c0     <= qr0) ? sacc[j][0] * scale : -1e30f;
                sacc[j][1] = (c0 + 1 <= qr0) ? sacc[j][1] * scale : -1e30f;
                sacc[j][2] = (c0     <= qr1) ? sacc[j][2] * scale : -1e30f;
                sacc[j][3] = (c0 + 1 <= qr1) ? sacc[j][3] * scale : -1e30f;
                mx0 = fmaxf(mx0, fmaxf(sacc[j][0], sacc[j][1]));
                mx1 = fmaxf(mx1, fmaxf(sacc[j][2], sacc[j][3]));
            }
        }
        mx0 = fmaxf(mx0, __shfl_xor_sync(0xffffffffu, mx0, 1));
        mx0 = fmaxf(mx0, __shfl_xor_sync(0xffffffffu, mx0, 2));
        mx1 = fmaxf(mx1, __shfl_xor_sync(0xffffffffu, mx1, 1));
        mx1 = fmaxf(mx1, __shfl_xor_sync(0xffffffffu, mx1, 2));

        float mn0 = fmaxf(m0, mx0), mn1 = fmaxf(m1, mx1);
        float f0 = exp2f(m0 - mn0), f1 = exp2f(m1 - mn1);
        m0 = mn0; m1 = mn1;

        // exp2 + pack P into A-fragments (C->A register layout identity)
        unsigned pa[8][4];
        float s0 = 0.f, s1 = 0.f;
        #pragma unroll
        for (int j2 = 0; j2 < 8; j2++) {
            float p00 = exp2f(sacc[2*j2][0]   - mn0);
            float p01 = exp2f(sacc[2*j2][1]   - mn0);
            float p02 = exp2f(sacc[2*j2][2]   - mn1);
            float p03 = exp2f(sacc[2*j2][3]   - mn1);
            float p10 = exp2f(sacc[2*j2+1][0] - mn0);
            float p11 = exp2f(sacc[2*j2+1][1] - mn0);
            float p12 = exp2f(sacc[2*j2+1][2] - mn1);
            float p13 = exp2f(sacc[2*j2+1][3] - mn1);
            s0 += p00 + p01 + p10 + p11;
            s1 += p02 + p03 + p12 + p13;
            pa[j2][0] = packh2(p00, p01);
            pa[j2][1] = packh2(p02, p03);
            pa[j2][2] = packh2(p10, p11);
            pa[j2][3] = packh2(p12, p13);
        }
        s0 += __shfl_xor_sync(0xffffffffu, s0, 1);
        s0 += __shfl_xor_sync(0xffffffffu, s0, 2);
        s1 += __shfl_xor_sync(0xffffffffu, s1, 1);
        s1 += __shfl_xor_sync(0xffffffffu, s1, 2);
        l0 = l0 * f0 + s0;
        l1 = l1 * f1 + s1;

        #pragma unroll
        for (int n = 0; n < 16; n++) {
            o[n][0] *= f0; o[n][1] *= f0; o[n][2] *= f1; o[n][3] *= f1;
        }

        // ---- PV: O += P V (16 rows x 128 cols per warp), P from registers ----
        #pragma unroll
        for (int ks = 0; ks < 8; ks++) {
            int kk = ks * 16;
            #pragma unroll
            for (int n = 0; n < 16; n += 2) {
                unsigned bb[4];
                ldm_x4t(bb, V + (kk + v_r) * VSTRH + n * 8 + v_c);
                mma16(o[n],     pa[ks], bb);
                mma16(o[n + 1], pa[ks], bb + 2);
            }
        }
    }

    // epilogue -> half
    float inv0 = 1.f / l0, inv1 = 1.f / l1;
    size_t r0 = (size_t)(b * SS + qbase + wrow + gr) * (HH * VD);
    size_t r1 = r0 + 8 * (HH * VD);
    #pragma unroll
    for (int n = 0; n < 16; n++) {
        int cc = h * VD + n * 8 + 2 * tg;
        *(__half2*)(aoh + r0 + cc) = __floats2half2_rn(o[n][0] * inv0, o[n][1] * inv0);
        *(__half2*)(aoh + r1 + cc) = __floats2half2_rn(o[n][2] * inv1, o[n][3] * inv1);
    }
}

// ---------------------------------------------------------------------------
extern "C" void kernel_launch(void* const* d_in, const int* in_sizes, int n_in,
                              void* d_out, int out_size) {
    const float* x     = (const float*)d_in[0];
    const float* wq    = (const float*)d_in[1];
    const float* wkv_a = (const float*)d_in[2];
    const float* wkv_b = (const float*)d_in[3];
    const float* wo    = (const float*)d_in[4];
    const float* kvs   = (const float*)d_in[5];
    float* out = (float*)d_out;

    float *cs;
    __half *qkvah, *kpeh, *ckvh, *kvh, *aoh, *xh, *wqaT, *wkvbT, *woT;
    cudaGetSymbolAddress((void**)&qkvah, g_qkvah);
    cudaGetSymbolAddress((void**)&cs,    g_cs);
    cudaGetSymbolAddress((void**)&kpeh,  g_kpeh);
    cudaGetSymbolAddress((void**)&ckvh,  g_ckvh);
    cudaGetSymbolAddress((void**)&kvh,   g_kvh);
    cudaGetSymbolAddress((void**)&aoh,   g_aoh);
    cudaGetSymbolAddress((void**)&xh,    g_xh);
    cudaGetSymbolAddress((void**)&wqaT,  g_wqaT);
    cudaGetSymbolAddress((void**)&wkvbT, g_wkvbT);
    cudaGetSymbolAddress((void**)&woT,   g_woT);

    static bool attr_done = false;
    if (!attr_done) {
        cudaFuncSetAttribute(flash_h,
                             cudaFuncAttributeMaxDynamicSharedMemorySize, (int)FSMEM);
        cudaFuncSetAttribute(hgemm<float>,
                             cudaFuncAttributeMaxDynamicSharedMemorySize, (int)GSMEM);
        cudaFuncSetAttribute(hgemm<__half>,
                             cudaFuncAttributeMaxDynamicSharedMemorySize, (int)GSMEM);
        attr_done = true;
    }

    // fused prep: f2h + cs table + all transposes in one launch
    prep_all<<<PREP_GRID, 256>>>(x, wq, wkv_a, wkv_b, wo, xh, wqaT, wkvbT, woT, cs);

    // qkva = x @ [wq | wkv_a] : [4096, 3712] half
    hgemm<__half><<<dim3(QAW / 128, 32), 256, GSMEM>>>(xh, wqaT, qkvah, QAW, 2048);
    // fused rmsnorm + in-place q rope + k_pe rope
    norm_rope<<<RWS, 128>>>(qkvah, kvs, cs, ckvh, kpeh);
    // kvh = ckv @ wkv_b : [4096, 4096] half
    hgemm<__half><<<dim3(32, 32), 256, GSMEM>>>(ckvh, wkvbT, kvh, 4096, 512);
    // attention -> aoh : [4096, 2048] half
    flash_h<<<dim3(SS / FBM, HH, BB), 256, FSMEM>>>(qkvah, kvh, kpeh, aoh);
    // out = ao @ wo : [4096, 2048] fp32
    hgemm<float><<<dim3(16, 32), 256, GSMEM>>>(aoh, woT, out, 2048, 2048);
}